// round 3
// baseline (speedup 1.0000x reference)
#include <cuda_runtime.h>

// WaterLevelLSTM: B independent chains, T=5, H=64. fp32-FMA-bound.
// R3: fix the shared-pipe bottleneck found in R1 (L1 84.6% vs fma 45.2%).
// Each thread owns TWO gate rows (t and t+128) with both W_hh rows packed
// in registers as f32x2 pairs -> every broadcast LDS.128 of h now feeds
// 4 FFMA2 instead of 2, halving shared-pipe pressure. 2 CTAs/SM overlap
// the MUFU activation phase with the other CTA's FFMA2 stream.

#define H        64
#define G        256
#define TSTEPS   5
#define NB       16
#define NTH      128

typedef unsigned long long u64;

__device__ __forceinline__ u64 fma2(u64 a, u64 b, u64 c) {
    u64 d;
    asm("fma.rn.f32x2 %0, %1, %2, %3;" : "=l"(d) : "l"(a), "l"(b), "l"(c));
    return d;
}
__device__ __forceinline__ u64 add2(u64 a, u64 b) {
    u64 d;
    asm("add.rn.f32x2 %0, %1, %2;" : "=l"(d) : "l"(a), "l"(b));
    return d;
}
__device__ __forceinline__ float2 unpk2(u64 a) {
    float lo, hi;
    asm("mov.b64 {%0,%1}, %2;" : "=f"(lo), "=f"(hi) : "l"(a));
    return make_float2(lo, hi);
}
__device__ __forceinline__ u64 pk2(float lo, float hi) {
    u64 r;
    asm("mov.b64 %0, {%1,%2};" : "=l"(r) : "f"(lo), "f"(hi));
    return r;
}

// accurate MUFU-based sigmoid/tanh (EX2 ~2^-22 rel err); NOT tanh.approx
__device__ __forceinline__ float sigmoid_f(float x) {
    return __fdividef(1.0f, 1.0f + __expf(-x));
}
__device__ __forceinline__ float tanh_f(float x) {
    return __fdividef(2.0f, 1.0f + __expf(-2.0f * x)) - 1.0f;
}

__global__ __launch_bounds__(NTH, 2)
void lstm_kernel(const float* __restrict__ x,
                 const float* __restrict__ W_ih,
                 const float* __restrict__ W_hh,
                 const float* __restrict__ b_ih,
                 const float* __restrict__ b_hh,
                 const float* __restrict__ W_fc,
                 const float* __restrict__ b_fc,
                 float* __restrict__ out,
                 int B)
{
    __shared__ __align__(16) float h_s[NB][H];
    __shared__ __align__(16) float c_s[NB][H];
    __shared__ float g_s[NB][G];
    __shared__ float x_s[NB * TSTEPS];
    __shared__ float wfc_s[H];

    const int t  = threadIdx.x;      // owns gate rows r0 = t, r1 = t + 128
    const int r1 = t + NTH;
    // r0 gtype = t>>6 in {0,1}  -> sigmoid always
    // r1 gtype = 2 + (t>>6)     -> tanh for t<64 (g gate), sigmoid for t>=64
    const bool r1_tanh = (t < 64);

    // ---- per-thread constant weights: 2 rows x 32 f32x2 pairs = 128 regs ----
    u64 Wa[H / 2], Wb[H / 2];
    {
        const float2* wr0 = reinterpret_cast<const float2*>(W_hh + t  * H);
        const float2* wr1 = reinterpret_cast<const float2*>(W_hh + r1 * H);
#pragma unroll
        for (int k = 0; k < H / 2; k++) {
            float2 v0 = wr0[k];
            float2 v1 = wr1[k];
            Wa[k] = pk2(v0.x, v0.y);
            Wb[k] = pk2(v1.x, v1.y);
        }
    }
    const float wih0  = W_ih[t];
    const float wih1  = W_ih[r1];
    const float bias0 = b_ih[t]  + b_hh[t];
    const float bias1 = b_ih[r1] + b_hh[r1];
    const float bfc   = b_fc[0];
    if (t < H) wfc_s[t] = W_fc[t];

    // ---- grid-stride over batch tiles ----
    for (int tile = blockIdx.x; ; tile += gridDim.x) {
        const int b0 = tile * NB;
        if (b0 >= B) break;

        for (int i = t; i < NB * H; i += NTH) {
            (&h_s[0][0])[i] = 0.0f;
            (&c_s[0][0])[i] = 0.0f;
        }
        if (t < NB * TSTEPS) {
            int gi = b0 * TSTEPS + t;
            x_s[t] = (gi < B * TSTEPS) ? x[gi] : 0.0f;
        }
        __syncthreads();

#pragma unroll 1
        for (int step = 0; step < TSTEPS; step++) {
            // ---- gate matvec: both rows share each broadcast h load ----
#pragma unroll 1
            for (int b = 0; b < NB; b++) {
                const ulonglong2* hp =
                    reinterpret_cast<const ulonglong2*>(&h_s[b][0]);
                u64 a0 = 0ull, a1 = 0ull, a2 = 0ull, a3 = 0ull;   // row r0
                u64 c0 = 0ull, c1 = 0ull, c2 = 0ull, c3 = 0ull;   // row r1
#pragma unroll
                for (int k = 0; k < H / 4; k += 2) {
                    ulonglong2 v0 = hp[k];        // 4 h values (broadcast)
                    ulonglong2 v1 = hp[k + 1];
                    a0 = fma2(Wa[2 * k + 0], v0.x, a0);
                    c0 = fma2(Wb[2 * k + 0], v0.x, c0);
                    a1 = fma2(Wa[2 * k + 1], v0.y, a1);
                    c1 = fma2(Wb[2 * k + 1], v0.y, c1);
                    a2 = fma2(Wa[2 * k + 2], v1.x, a2);
                    c2 = fma2(Wb[2 * k + 2], v1.x, c2);
                    a3 = fma2(Wa[2 * k + 3], v1.y, a3);
                    c3 = fma2(Wb[2 * k + 3], v1.y, c3);
                }
                float2 s0 = unpk2(add2(add2(a0, a1), add2(a2, a3)));
                float2 s1 = unpk2(add2(add2(c0, c1), add2(c2, c3)));
                float xs = x_s[b * TSTEPS + step];
                float gate0 = fmaf(xs, wih0, bias0) + s0.x + s0.y;
                float gate1 = fmaf(xs, wih1, bias1) + s1.x + s1.y;
                g_s[b][t]  = sigmoid_f(gate0);                       // i or f
                g_s[b][r1] = r1_tanh ? tanh_f(gate1)
                                     : sigmoid_f(gate1);             // g or o
            }
            __syncthreads();

            // ---- state update: 8 (b, j) units per thread ----
#pragma unroll
            for (int p = 0; p < (NB * H) / NTH; p++) {
                int idx = t + p * NTH;
                int b = idx >> 6;
                int j = idx & (H - 1);
                float iv = g_s[b][0 * H + j];
                float fv = g_s[b][1 * H + j];
                float gv = g_s[b][2 * H + j];
                float ov = g_s[b][3 * H + j];
                float c  = fmaf(fv, c_s[b][j], iv * gv);
                c_s[b][j] = c;
                h_s[b][j] = ov * tanh_f(c);
            }
            __syncthreads();
        }

        // ---- output head ----
        if (t < NB && (b0 + t) < B) {
            float acc = 0.0f;
#pragma unroll
            for (int j = 0; j < H; j++)
                acc = fmaf(h_s[t][j], wfc_s[j], acc);
            out[b0 + t] = acc + bfc;
        }
        __syncthreads();
    }
}

extern "C" void kernel_launch(void* const* d_in, const int* in_sizes, int n_in,
                              void* d_out, int out_size) {
    const float* x    = (const float*)d_in[0];
    const float* W_ih = (const float*)d_in[1];
    const float* W_hh = (const float*)d_in[2];
    const float* b_ih = (const float*)d_in[3];
    const float* b_hh = (const float*)d_in[4];
    const float* W_fc = (const float*)d_in[5];
    const float* b_fc = (const float*)d_in[6];
    float* out = (float*)d_out;

    const int B = in_sizes[0] / TSTEPS;   // x is [B, T, 1]
    int tiles = (B + NB - 1) / NB;
    int grid = tiles < 1024 ? tiles : 1024;

    lstm_kernel<<<grid, NTH>>>(x, W_ih, W_hh, b_ih, b_hh, W_fc, b_fc, out, B);
}